// round 13
// baseline (speedup 1.0000x reference)
#include <cuda_runtime.h>
#include <math.h>

#define N_USERS 20000
#define N_ENT   80000
#define N_NODES (N_USERS + N_ENT)
#define D       64
#define E_MAX   1250000
#define EPS_ATT 1e-9f
#define EPS_NORM 1e-12f

#define SCAN_BLK 1024
#define N_SCAN_BLOCKS ((N_NODES + SCAN_BLK - 1) / SCAN_BLK)   // 98

// Scratch (__device__ globals; no allocation allowed)
__device__ __align__(16) float g_ego [(size_t)N_NODES * D];
__device__ __align__(16) float g_sum [(size_t)N_NODES * D];
__device__ __align__(16) float g_aggr[(size_t)N_NODES * D];
__device__ int  g_hist    [N_NODES];     // zero-init; re-zeroed by k_scan_a each launch
__device__ int  g_segstart[N_NODES + 1];
__device__ int  g_cursor  [N_NODES];
__device__ int2 g_dr      [E_MAX];       // sorted (dst, rel) per edge
__device__ int  g_bsum    [N_SCAN_BLOCKS];

// ---------------------------------------------------------------------------
// Init (fused with histogram)
// ---------------------------------------------------------------------------
__global__ void k_init(const float* __restrict__ ue, const float* __restrict__ ee,
                       const int* __restrict__ src, int nE) {
    size_t i = (size_t)blockIdx.x * blockDim.x + threadIdx.x;
    const size_t NU = (size_t)N_USERS * D;
    const size_t NT = (size_t)N_NODES * D;
    if (i < NT) {
        float v = (i < NU) ? ue[i] : ee[i - NU];
        g_ego[i] = v;
        g_sum[i] = v;
    }
    if (i < (size_t)nE) atomicAdd(&g_hist[src[i]], 1);
}

// ---------------------------------------------------------------------------
// Two-level exclusive scan of hist -> segstart (block-sum scan fused in scan_c)
// ---------------------------------------------------------------------------
__global__ void k_scan_a() {
    __shared__ int s[SCAN_BLK];
    int t = threadIdx.x;
    int i = blockIdx.x * SCAN_BLK + t;
    int v = (i < N_NODES) ? g_hist[i] : 0;
    if (i < N_NODES) g_hist[i] = 0;                       // re-zero for next launch
    s[t] = v;
    __syncthreads();
    #pragma unroll
    for (int o = 1; o < SCAN_BLK; o <<= 1) {
        int add = (t >= o) ? s[t - o] : 0;
        __syncthreads();
        s[t] += add;
        __syncthreads();
    }
    if (i < N_NODES) g_segstart[i] = s[t] - v;            // exclusive within block
    if (t == SCAN_BLK - 1) g_bsum[blockIdx.x] = s[t];     // block total
}

__global__ void k_scan_c(int nE) {
    // all 256 indices of this block lie in one SCAN_BLK region
    __shared__ int sred[256];
    int t = threadIdx.x;
    int region = (blockIdx.x * 256) / SCAN_BLK;           // # of preceding scan blocks
    int p = (t < region) ? g_bsum[t] : 0;                 // region <= 97 < 256
    sred[t] = p;
    __syncthreads();
    #pragma unroll
    for (int o = 128; o; o >>= 1) {
        if (t < o) sred[t] += sred[t + o];
        __syncthreads();
    }
    int boff = sred[0];
    int i = blockIdx.x * 256 + t;
    if (i < N_NODES) {
        int v = g_segstart[i] + boff;
        g_segstart[i] = v;
        g_cursor[i]   = v;
    }
    if (i == 0) g_segstart[N_NODES] = nE;
}

__global__ void k_permute(const int* __restrict__ src, const int* __restrict__ dst,
                          const int* __restrict__ rel, int nE) {
    int e = blockIdx.x * blockDim.x + threadIdx.x;
    if (e < nE) {
        int pos = atomicAdd(&g_cursor[src[e]], 1);
        g_dr[pos] = make_int2(dst[e], rel[e]);
    }
}

// ---------------------------------------------------------------------------
// Fused attention layer: one warp per source node, float2/lane, edge loop
// unrolled x4 with 4 independent shuffle-reduce chains.
//   aggr[n] = (sum_e t_e * ex_e) / (sum_e ex_e + eps),  ex_e = exp(lrelu(h.t.r))
// ---------------------------------------------------------------------------
__global__ void k_edge(const float* __restrict__ rel_emb) {
    int gw   = (blockIdx.x * blockDim.x + threadIdx.x) >> 5;
    int lane = threadIdx.x & 31;
    if (gw >= N_NODES) return;

    int beg = g_segstart[gw];
    int end = g_segstart[gw + 1];
    if (beg == end) {
        *(float2*)(g_aggr + (size_t)gw * D + lane * 2) = make_float2(0.f, 0.f);
        return;
    }

    float2 h = *(const float2*)(g_ego + (size_t)gw * D + lane * 2);
    float denom = 0.f;
    float accx = 0.f, accy = 0.f;

    for (int e0 = beg; e0 < end; e0 += 4) {
        int  e1 = e0 + 1, e2 = e0 + 2, e3 = e0 + 3;
        bool v1 = e1 < end, v2 = e2 < end, v3 = e3 < end;
        int2 d0 = __ldg(&g_dr[e0]);
        int2 d1 = __ldg(&g_dr[v1 ? e1 : beg]);
        int2 d2 = __ldg(&g_dr[v2 ? e2 : beg]);
        int2 d3 = __ldg(&g_dr[v3 ? e3 : beg]);

        float2 t0 = *(const float2*)(g_ego + (size_t)d0.x * D + lane * 2);
        float2 t1 = *(const float2*)(g_ego + (size_t)d1.x * D + lane * 2);
        float2 t2 = *(const float2*)(g_ego + (size_t)d2.x * D + lane * 2);
        float2 t3 = *(const float2*)(g_ego + (size_t)d3.x * D + lane * 2);
        float2 r0 = *(const float2*)(rel_emb + (size_t)d0.y * D + lane * 2);
        float2 r1 = *(const float2*)(rel_emb + (size_t)d1.y * D + lane * 2);
        float2 r2 = *(const float2*)(rel_emb + (size_t)d2.y * D + lane * 2);
        float2 r3 = *(const float2*)(rel_emb + (size_t)d3.y * D + lane * 2);

        float p0 = h.x * t0.x * r0.x;  p0 = fmaf(h.y * t0.y, r0.y, p0);
        float p1 = h.x * t1.x * r1.x;  p1 = fmaf(h.y * t1.y, r1.y, p1);
        float p2 = h.x * t2.x * r2.x;  p2 = fmaf(h.y * t2.y, r2.y, p2);
        float p3 = h.x * t3.x * r3.x;  p3 = fmaf(h.y * t3.y, r3.y, p3);

        #pragma unroll
        for (int o = 16; o; o >>= 1) {
            p0 += __shfl_xor_sync(0xffffffffu, p0, o);
            p1 += __shfl_xor_sync(0xffffffffu, p1, o);
            p2 += __shfl_xor_sync(0xffffffffu, p2, o);
            p3 += __shfl_xor_sync(0xffffffffu, p3, o);
        }

        float l0 = p0 > 0.f ? p0 : 0.01f * p0;
        float l1 = p1 > 0.f ? p1 : 0.01f * p1;
        float l2 = p2 > 0.f ? p2 : 0.01f * p2;
        float l3 = p3 > 0.f ? p3 : 0.01f * p3;
        float x0 = __expf(l0);
        float x1 = v1 ? __expf(l1) : 0.f;
        float x2 = v2 ? __expf(l2) : 0.f;
        float x3 = v3 ? __expf(l3) : 0.f;

        denom += (x0 + x1) + (x2 + x3);
        accx = fmaf(t0.x, x0, accx);  accx = fmaf(t1.x, x1, accx);
        accx = fmaf(t2.x, x2, accx);  accx = fmaf(t3.x, x3, accx);
        accy = fmaf(t0.y, x0, accy);  accy = fmaf(t1.y, x1, accy);
        accy = fmaf(t2.y, x2, accy);  accy = fmaf(t3.y, x3, accy);
    }

    float inv = 1.f / (denom + EPS_ATT);
    *(float2*)(g_aggr + (size_t)gw * D + lane * 2) = make_float2(accx * inv, accy * inv);
}

// ---------------------------------------------------------------------------
// Node update: new = lrelu((ego+aggr)@W1 + (ego*aggr)@W2); L2-normalize.
// 32 nodes/block, 8 threads/node x 8 cols each (W broadcast 4 nodes/warp).
// Non-final: ego = new, sum += new.   Final: out = (sum+new)/3 permuted.
// ---------------------------------------------------------------------------
#define NPB 32
#define NODE_SMEM (2 * D * D * 4 + 2 * NPB * D * 4)   // 32KB W + 16KB X = 48KB

template <bool FINAL>
__global__ __launch_bounds__(256, 4)
void k_node(const float* __restrict__ W1, const float* __restrict__ W2,
            float* __restrict__ out) {
    extern __shared__ float sm[];
    float* W1s = sm;                    // [64][64]
    float* W2s = sm + D * D;            // [64][64]
    float* xs  = sm + 2 * D * D;        // [NPB][64]
    float* ys  = xs + NPB * D;          // [NPB][64]

    int tid  = threadIdx.x;
    int base = blockIdx.x * NPB;

    #pragma unroll
    for (int i = 0; i < 16; i++) {
        int idx = tid + i * 256;
        W1s[idx] = W1[idx];
        W2s[idx] = W2[idx];
    }
    #pragma unroll
    for (int i = 0; i < 8; i++) {
        int idx = tid + i * 256;        // 0..2047 over [32 nodes][64 dims]
        int ln = idx >> 6, c = idx & 63;
        int n = base + ln;
        float eg = 0.f, ag = 0.f;
        if (n < N_NODES) {
            eg = g_ego [(size_t)n * D + c];
            ag = g_aggr[(size_t)n * D + c];
        }
        xs[ln * D + c] = eg + ag;
        ys[ln * D + c] = eg * ag;
    }
    __syncthreads();

    int ln = tid >> 3;                  // node within block (0..31)
    int c0 = (tid & 7) * 8;             // 8 output columns per thread
    int n  = base + ln;

    float a[8] = {0.f, 0.f, 0.f, 0.f, 0.f, 0.f, 0.f, 0.f};
    #pragma unroll 8
    for (int k = 0; k < D; k++) {
        float xk = xs[ln * D + k];
        float yk = ys[ln * D + k];
        float4 w1a = *(const float4*)&W1s[k * D + c0];
        float4 w1b = *(const float4*)&W1s[k * D + c0 + 4];
        float4 w2a = *(const float4*)&W2s[k * D + c0];
        float4 w2b = *(const float4*)&W2s[k * D + c0 + 4];
        a[0] = fmaf(xk, w1a.x, a[0]); a[1] = fmaf(xk, w1a.y, a[1]);
        a[2] = fmaf(xk, w1a.z, a[2]); a[3] = fmaf(xk, w1a.w, a[3]);
        a[4] = fmaf(xk, w1b.x, a[4]); a[5] = fmaf(xk, w1b.y, a[5]);
        a[6] = fmaf(xk, w1b.z, a[6]); a[7] = fmaf(xk, w1b.w, a[7]);
        a[0] = fmaf(yk, w2a.x, a[0]); a[1] = fmaf(yk, w2a.y, a[1]);
        a[2] = fmaf(yk, w2a.z, a[2]); a[3] = fmaf(yk, w2a.w, a[3]);
        a[4] = fmaf(yk, w2b.x, a[4]); a[5] = fmaf(yk, w2b.y, a[5]);
        a[6] = fmaf(yk, w2b.z, a[6]); a[7] = fmaf(yk, w2b.w, a[7]);
    }

    float sq = 0.f;
    #pragma unroll
    for (int j = 0; j < 8; j++) {
        a[j] = a[j] > 0.f ? a[j] : 0.01f * a[j];
        sq = fmaf(a[j], a[j], sq);
    }
    // reduce over the 8 threads of this node (consecutive lanes: xor 1,2,4)
    sq += __shfl_xor_sync(0xffffffffu, sq, 1);
    sq += __shfl_xor_sync(0xffffffffu, sq, 2);
    sq += __shfl_xor_sync(0xffffffffu, sq, 4);
    float inv = 1.f / fmaxf(sqrtf(sq), EPS_NORM);
    #pragma unroll
    for (int j = 0; j < 8; j++) a[j] *= inv;

    if (n < N_NODES) {
        size_t o = (size_t)n * D + c0;
        float4 s0 = *(const float4*)&g_sum[o];
        float4 s1 = *(const float4*)&g_sum[o + 4];
        if (FINAL) {
            size_t orow = (n >= N_USERS) ? (size_t)(n - N_USERS)
                                         : (size_t)(N_ENT + n);
            float* op = out + orow * D + c0;
            *(float4*)op       = make_float4((s0.x + a[0]) * (1.f / 3.f),
                                             (s0.y + a[1]) * (1.f / 3.f),
                                             (s0.z + a[2]) * (1.f / 3.f),
                                             (s0.w + a[3]) * (1.f / 3.f));
            *(float4*)(op + 4) = make_float4((s1.x + a[4]) * (1.f / 3.f),
                                             (s1.y + a[5]) * (1.f / 3.f),
                                             (s1.z + a[6]) * (1.f / 3.f),
                                             (s1.w + a[7]) * (1.f / 3.f));
        } else {
            *(float4*)&g_ego[o]     = make_float4(a[0], a[1], a[2], a[3]);
            *(float4*)&g_ego[o + 4] = make_float4(a[4], a[5], a[6], a[7]);
            *(float4*)&g_sum[o]     = make_float4(s0.x + a[0], s0.y + a[1],
                                                  s0.z + a[2], s0.w + a[3]);
            *(float4*)&g_sum[o + 4] = make_float4(s1.x + a[4], s1.y + a[5],
                                                  s1.z + a[6], s1.w + a[7]);
        }
    }
}

// ---------------------------------------------------------------------------
extern "C" void kernel_launch(void* const* d_in, const int* in_sizes, int n_in,
                              void* d_out, int out_size) {
    const float* user_emb = (const float*)d_in[0];
    const float* ent_emb  = (const float*)d_in[1];
    const float* rel_emb  = (const float*)d_in[2];
    const float* W1       = (const float*)d_in[3];
    const float* W2       = (const float*)d_in[4];
    const int*   src      = (const int*)d_in[5];
    const int*   dst      = (const int*)d_in[6];
    const int*   rel      = (const int*)d_in[7];
    float* out = (float*)d_out;

    int nE = in_sizes[5];
    if (nE > E_MAX) nE = E_MAX;

    static bool attr_done = false;
    if (!attr_done) {
        cudaFuncSetAttribute(k_node<false>, cudaFuncAttributeMaxDynamicSharedMemorySize, NODE_SMEM);
        cudaFuncSetAttribute(k_node<true>,  cudaFuncAttributeMaxDynamicSharedMemorySize, NODE_SMEM);
        attr_done = true;
    }

    const int nodeElems = N_NODES * D;
    int initBlocks = (nodeElems + 255) / 256;       // covers nE too
    int eBlocks    = (nE + 255) / 256;
    int segBlocks  = (N_NODES + 255) / 256;
    int edgeBlocks = (N_NODES * 32 + 255) / 256;    // warp per node
    int nodeBlocks = (N_NODES + NPB - 1) / NPB;

    k_init<<<initBlocks, 256>>>(user_emb, ent_emb, src, nE);
    k_scan_a<<<N_SCAN_BLOCKS, SCAN_BLK>>>();
    k_scan_c<<<segBlocks, 256>>>(nE);
    k_permute<<<eBlocks, 256>>>(src, dst, rel, nE);

    k_edge<<<edgeBlocks, 256>>>(rel_emb);
    k_node<false><<<nodeBlocks, 256, NODE_SMEM>>>(W1, W2, out);
    k_edge<<<edgeBlocks, 256>>>(rel_emb);
    k_node<true><<<nodeBlocks, 256, NODE_SMEM>>>(W1, W2, out);
}

// round 14
// speedup vs baseline: 1.0028x; 1.0028x over previous
#include <cuda_runtime.h>
#include <math.h>

#define N_USERS 20000
#define N_ENT   80000
#define N_NODES (N_USERS + N_ENT)
#define D       64
#define E_MAX   1250000
#define EPS_ATT 1e-9f
#define EPS_NORM 1e-12f

#define SCAN_BLK 1024
#define N_SCAN_BLOCKS ((N_NODES + SCAN_BLK - 1) / SCAN_BLK)   // 98

// Scratch (__device__ globals; no allocation allowed)
__device__ __align__(16) float g_ego [(size_t)N_NODES * D];
__device__ __align__(16) float g_sum [(size_t)N_NODES * D];
__device__ __align__(16) float g_aggr[(size_t)N_NODES * D];
__device__ int  g_hist    [N_NODES];     // zero-init; re-zeroed by k_scan_a each launch
__device__ int  g_segstart[N_NODES + 1];
__device__ int  g_cursor  [N_NODES];
__device__ int2 g_dr      [E_MAX];       // sorted (dst, rel) per edge
__device__ int  g_bsum    [N_SCAN_BLOCKS];

// ---------------------------------------------------------------------------
// Init (fused with histogram)
// ---------------------------------------------------------------------------
__global__ void k_init(const float* __restrict__ ue, const float* __restrict__ ee,
                       const int* __restrict__ src, int nE) {
    size_t i = (size_t)blockIdx.x * blockDim.x + threadIdx.x;
    const size_t NU = (size_t)N_USERS * D;
    const size_t NT = (size_t)N_NODES * D;
    if (i < NT) {
        float v = (i < NU) ? ue[i] : ee[i - NU];
        g_ego[i] = v;
        g_sum[i] = v;
    }
    if (i < (size_t)nE) atomicAdd(&g_hist[src[i]], 1);
}

// ---------------------------------------------------------------------------
// Two-level exclusive scan of hist -> segstart (block-sum scan fused in scan_c)
// ---------------------------------------------------------------------------
__global__ void k_scan_a() {
    __shared__ int s[SCAN_BLK];
    int t = threadIdx.x;
    int i = blockIdx.x * SCAN_BLK + t;
    int v = (i < N_NODES) ? g_hist[i] : 0;
    if (i < N_NODES) g_hist[i] = 0;                       // re-zero for next launch
    s[t] = v;
    __syncthreads();
    #pragma unroll
    for (int o = 1; o < SCAN_BLK; o <<= 1) {
        int add = (t >= o) ? s[t - o] : 0;
        __syncthreads();
        s[t] += add;
        __syncthreads();
    }
    if (i < N_NODES) g_segstart[i] = s[t] - v;            // exclusive within block
    if (t == SCAN_BLK - 1) g_bsum[blockIdx.x] = s[t];     // block total
}

__global__ void k_scan_c(int nE) {
    // all 256 indices of this block lie in one SCAN_BLK region
    __shared__ int sred[256];
    int t = threadIdx.x;
    int region = (blockIdx.x * 256) / SCAN_BLK;           // # of preceding scan blocks
    int p = (t < region) ? g_bsum[t] : 0;                 // region <= 97 < 256
    sred[t] = p;
    __syncthreads();
    #pragma unroll
    for (int o = 128; o; o >>= 1) {
        if (t < o) sred[t] += sred[t + o];
        __syncthreads();
    }
    int boff = sred[0];
    int i = blockIdx.x * 256 + t;
    if (i < N_NODES) {
        int v = g_segstart[i] + boff;
        g_segstart[i] = v;
        g_cursor[i]   = v;
    }
    if (i == 0) g_segstart[N_NODES] = nE;
}

__global__ void k_permute(const int* __restrict__ src, const int* __restrict__ dst,
                          const int* __restrict__ rel, int nE) {
    int e = blockIdx.x * blockDim.x + threadIdx.x;
    if (e < nE) {
        int pos = atomicAdd(&g_cursor[src[e]], 1);
        g_dr[pos] = make_int2(dst[e], rel[e]);
    }
}

// ---------------------------------------------------------------------------
// Fused attention layer: one warp per source node, float2/lane, edge loop
// unrolled x4 with 4 independent shuffle-reduce chains.
//   aggr[n] = (sum_e t_e * ex_e) / (sum_e ex_e + eps),  ex_e = exp(lrelu(h.t.r))
// ---------------------------------------------------------------------------
__global__ void k_edge(const float* __restrict__ rel_emb) {
    int gw   = (blockIdx.x * blockDim.x + threadIdx.x) >> 5;
    int lane = threadIdx.x & 31;
    if (gw >= N_NODES) return;

    int beg = g_segstart[gw];
    int end = g_segstart[gw + 1];
    if (beg == end) {
        *(float2*)(g_aggr + (size_t)gw * D + lane * 2) = make_float2(0.f, 0.f);
        return;
    }

    float2 h = *(const float2*)(g_ego + (size_t)gw * D + lane * 2);
    float denom = 0.f;
    float accx = 0.f, accy = 0.f;

    for (int e0 = beg; e0 < end; e0 += 4) {
        int  e1 = e0 + 1, e2 = e0 + 2, e3 = e0 + 3;
        bool v1 = e1 < end, v2 = e2 < end, v3 = e3 < end;
        int2 d0 = __ldg(&g_dr[e0]);
        int2 d1 = __ldg(&g_dr[v1 ? e1 : beg]);
        int2 d2 = __ldg(&g_dr[v2 ? e2 : beg]);
        int2 d3 = __ldg(&g_dr[v3 ? e3 : beg]);

        float2 t0 = *(const float2*)(g_ego + (size_t)d0.x * D + lane * 2);
        float2 t1 = *(const float2*)(g_ego + (size_t)d1.x * D + lane * 2);
        float2 t2 = *(const float2*)(g_ego + (size_t)d2.x * D + lane * 2);
        float2 t3 = *(const float2*)(g_ego + (size_t)d3.x * D + lane * 2);
        float2 r0 = *(const float2*)(rel_emb + (size_t)d0.y * D + lane * 2);
        float2 r1 = *(const float2*)(rel_emb + (size_t)d1.y * D + lane * 2);
        float2 r2 = *(const float2*)(rel_emb + (size_t)d2.y * D + lane * 2);
        float2 r3 = *(const float2*)(rel_emb + (size_t)d3.y * D + lane * 2);

        float p0 = h.x * t0.x * r0.x;  p0 = fmaf(h.y * t0.y, r0.y, p0);
        float p1 = h.x * t1.x * r1.x;  p1 = fmaf(h.y * t1.y, r1.y, p1);
        float p2 = h.x * t2.x * r2.x;  p2 = fmaf(h.y * t2.y, r2.y, p2);
        float p3 = h.x * t3.x * r3.x;  p3 = fmaf(h.y * t3.y, r3.y, p3);

        #pragma unroll
        for (int o = 16; o; o >>= 1) {
            p0 += __shfl_xor_sync(0xffffffffu, p0, o);
            p1 += __shfl_xor_sync(0xffffffffu, p1, o);
            p2 += __shfl_xor_sync(0xffffffffu, p2, o);
            p3 += __shfl_xor_sync(0xffffffffu, p3, o);
        }

        float l0 = p0 > 0.f ? p0 : 0.01f * p0;
        float l1 = p1 > 0.f ? p1 : 0.01f * p1;
        float l2 = p2 > 0.f ? p2 : 0.01f * p2;
        float l3 = p3 > 0.f ? p3 : 0.01f * p3;
        float x0 = __expf(l0);
        float x1 = v1 ? __expf(l1) : 0.f;
        float x2 = v2 ? __expf(l2) : 0.f;
        float x3 = v3 ? __expf(l3) : 0.f;

        denom += (x0 + x1) + (x2 + x3);
        accx = fmaf(t0.x, x0, accx);  accx = fmaf(t1.x, x1, accx);
        accx = fmaf(t2.x, x2, accx);  accx = fmaf(t3.x, x3, accx);
        accy = fmaf(t0.y, x0, accy);  accy = fmaf(t1.y, x1, accy);
        accy = fmaf(t2.y, x2, accy);  accy = fmaf(t3.y, x3, accy);
    }

    float inv = 1.f / (denom + EPS_ATT);
    *(float2*)(g_aggr + (size_t)gw * D + lane * 2) = make_float2(accx * inv, accy * inv);
}

// ---------------------------------------------------------------------------
// Node update: new = lrelu((ego+aggr)@W1 + (ego*aggr)@W2); L2-normalize.
// 32 nodes/block, 8 threads/node x 8 cols each (W broadcast 4 nodes/warp).
// Non-final: ego = new, sum += new.   Final: out = (sum+new)/3 permuted.
// ---------------------------------------------------------------------------
#define NPB 32
#define NODE_SMEM (2 * D * D * 4 + 2 * NPB * D * 4)   // 32KB W + 16KB X = 48KB

template <bool FINAL>
__global__ __launch_bounds__(256, 4)
void k_node(const float* __restrict__ W1, const float* __restrict__ W2,
            float* __restrict__ out) {
    extern __shared__ float sm[];
    float* W1s = sm;                    // [64][64]
    float* W2s = sm + D * D;            // [64][64]
    float* xs  = sm + 2 * D * D;        // [NPB][64]
    float* ys  = xs + NPB * D;          // [NPB][64]

    int tid  = threadIdx.x;
    int base = blockIdx.x * NPB;

    #pragma unroll
    for (int i = 0; i < 16; i++) {
        int idx = tid + i * 256;
        W1s[idx] = W1[idx];
        W2s[idx] = W2[idx];
    }
    #pragma unroll
    for (int i = 0; i < 8; i++) {
        int idx = tid + i * 256;        // 0..2047 over [32 nodes][64 dims]
        int ln = idx >> 6, c = idx & 63;
        int n = base + ln;
        float eg = 0.f, ag = 0.f;
        if (n < N_NODES) {
            eg = g_ego [(size_t)n * D + c];
            ag = g_aggr[(size_t)n * D + c];
        }
        xs[ln * D + c] = eg + ag;
        ys[ln * D + c] = eg * ag;
    }
    __syncthreads();

    int ln = tid >> 3;                  // node within block (0..31)
    int c0 = (tid & 7) * 8;             // 8 output columns per thread
    int n  = base + ln;

    float a[8] = {0.f, 0.f, 0.f, 0.f, 0.f, 0.f, 0.f, 0.f};
    #pragma unroll 8
    for (int k = 0; k < D; k++) {
        float xk = xs[ln * D + k];
        float yk = ys[ln * D + k];
        float4 w1a = *(const float4*)&W1s[k * D + c0];
        float4 w1b = *(const float4*)&W1s[k * D + c0 + 4];
        float4 w2a = *(const float4*)&W2s[k * D + c0];
        float4 w2b = *(const float4*)&W2s[k * D + c0 + 4];
        a[0] = fmaf(xk, w1a.x, a[0]); a[1] = fmaf(xk, w1a.y, a[1]);
        a[2] = fmaf(xk, w1a.z, a[2]); a[3] = fmaf(xk, w1a.w, a[3]);
        a[4] = fmaf(xk, w1b.x, a[4]); a[5] = fmaf(xk, w1b.y, a[5]);
        a[6] = fmaf(xk, w1b.z, a[6]); a[7] = fmaf(xk, w1b.w, a[7]);
        a[0] = fmaf(yk, w2a.x, a[0]); a[1] = fmaf(yk, w2a.y, a[1]);
        a[2] = fmaf(yk, w2a.z, a[2]); a[3] = fmaf(yk, w2a.w, a[3]);
        a[4] = fmaf(yk, w2b.x, a[4]); a[5] = fmaf(yk, w2b.y, a[5]);
        a[6] = fmaf(yk, w2b.z, a[6]); a[7] = fmaf(yk, w2b.w, a[7]);
    }

    float sq = 0.f;
    #pragma unroll
    for (int j = 0; j < 8; j++) {
        a[j] = a[j] > 0.f ? a[j] : 0.01f * a[j];
        sq = fmaf(a[j], a[j], sq);
    }
    // reduce over the 8 threads of this node (consecutive lanes: xor 1,2,4)
    sq += __shfl_xor_sync(0xffffffffu, sq, 1);
    sq += __shfl_xor_sync(0xffffffffu, sq, 2);
    sq += __shfl_xor_sync(0xffffffffu, sq, 4);
    float inv = 1.f / fmaxf(sqrtf(sq), EPS_NORM);
    #pragma unroll
    for (int j = 0; j < 8; j++) a[j] *= inv;

    if (n < N_NODES) {
        size_t o = (size_t)n * D + c0;
        float4 s0 = *(const float4*)&g_sum[o];
        float4 s1 = *(const float4*)&g_sum[o + 4];
        if (FINAL) {
            size_t orow = (n >= N_USERS) ? (size_t)(n - N_USERS)
                                         : (size_t)(N_ENT + n);
            float* op = out + orow * D + c0;
            *(float4*)op       = make_float4((s0.x + a[0]) * (1.f / 3.f),
                                             (s0.y + a[1]) * (1.f / 3.f),
                                             (s0.z + a[2]) * (1.f / 3.f),
                                             (s0.w + a[3]) * (1.f / 3.f));
            *(float4*)(op + 4) = make_float4((s1.x + a[4]) * (1.f / 3.f),
                                             (s1.y + a[5]) * (1.f / 3.f),
                                             (s1.z + a[6]) * (1.f / 3.f),
                                             (s1.w + a[7]) * (1.f / 3.f));
        } else {
            *(float4*)&g_ego[o]     = make_float4(a[0], a[1], a[2], a[3]);
            *(float4*)&g_ego[o + 4] = make_float4(a[4], a[5], a[6], a[7]);
            *(float4*)&g_sum[o]     = make_float4(s0.x + a[0], s0.y + a[1],
                                                  s0.z + a[2], s0.w + a[3]);
            *(float4*)&g_sum[o + 4] = make_float4(s1.x + a[4], s1.y + a[5],
                                                  s1.z + a[6], s1.w + a[7]);
        }
    }
}

// ---------------------------------------------------------------------------
extern "C" void kernel_launch(void* const* d_in, const int* in_sizes, int n_in,
                              void* d_out, int out_size) {
    const float* user_emb = (const float*)d_in[0];
    const float* ent_emb  = (const float*)d_in[1];
    const float* rel_emb  = (const float*)d_in[2];
    const float* W1       = (const float*)d_in[3];
    const float* W2       = (const float*)d_in[4];
    const int*   src      = (const int*)d_in[5];
    const int*   dst      = (const int*)d_in[6];
    const int*   rel      = (const int*)d_in[7];
    float* out = (float*)d_out;

    int nE = in_sizes[5];
    if (nE > E_MAX) nE = E_MAX;

    static bool attr_done = false;
    if (!attr_done) {
        cudaFuncSetAttribute(k_node<false>, cudaFuncAttributeMaxDynamicSharedMemorySize, NODE_SMEM);
        cudaFuncSetAttribute(k_node<true>,  cudaFuncAttributeMaxDynamicSharedMemorySize, NODE_SMEM);
        attr_done = true;
    }

    const int nodeElems = N_NODES * D;
    int initBlocks = (nodeElems + 255) / 256;       // covers nE too
    int eBlocks    = (nE + 255) / 256;
    int segBlocks  = (N_NODES + 255) / 256;
    int edgeBlocks = (N_NODES * 32 + 255) / 256;    // warp per node
    int nodeBlocks = (N_NODES + NPB - 1) / NPB;

    k_init<<<initBlocks, 256>>>(user_emb, ent_emb, src, nE);
    k_scan_a<<<N_SCAN_BLOCKS, SCAN_BLK>>>();
    k_scan_c<<<segBlocks, 256>>>(nE);
    k_permute<<<eBlocks, 256>>>(src, dst, rel, nE);

    k_edge<<<edgeBlocks, 256>>>(rel_emb);
    k_node<false><<<nodeBlocks, 256, NODE_SMEM>>>(W1, W2, out);
    k_edge<<<edgeBlocks, 256>>>(rel_emb);
    k_node<true><<<nodeBlocks, 256, NODE_SMEM>>>(W1, W2, out);
}